// round 7
// baseline (speedup 1.0000x reference)
#include <cuda_runtime.h>
#include <cstdint>

#define NGROUP 80
#define BEX 8
#define NPG 1024
#define MCENT 512
#define NTHR 512
#define MAXIT 300
#define TOLF 1e-3f
#define EPS_D2 2e-4f      // bound on |F + p2 - d^2_true| (generous)
#define EPS_DR 1e-6f      // drift inflation
#define MARGIN 1e-3f      // skip margin in d^2 space (>> fp wobble)
#define FINF __int_as_float(0x7f800000)

// ---------------- device globals (no allocation allowed) ----------------
__device__ int g_flags[MAXIT + 1];
__device__ unsigned int g_bar_count;
__device__ unsigned int g_bar_gen;

// ---------------- threefry2x32 (exact JAX PRNG, partitionable) ----------------
__device__ __forceinline__ uint32_t rotl32(uint32_t x, int d) { return (x << d) | (x >> (32 - d)); }

__device__ __forceinline__ void tf2x32(uint32_t k0, uint32_t k1, uint32_t x0, uint32_t x1,
                                       uint32_t& o0, uint32_t& o1) {
    uint32_t ks0 = k0, ks1 = k1, ks2 = k0 ^ k1 ^ 0x1BD11BDAu;
#define RND(r) { x0 += x1; x1 = rotl32(x1, r); x1 ^= x0; }
    x0 += ks0; x1 += ks1;
    RND(13) RND(15) RND(26) RND(6)   x0 += ks1; x1 += ks2 + 1u;
    RND(17) RND(29) RND(16) RND(24)  x0 += ks2; x1 += ks0 + 2u;
    RND(13) RND(15) RND(26) RND(6)   x0 += ks0; x1 += ks1 + 3u;
    RND(17) RND(29) RND(16) RND(24)  x0 += ks1; x1 += ks2 + 4u;
    RND(13) RND(15) RND(26) RND(6)   x0 += ks2; x1 += ks0 + 5u;
#undef RND
    o0 = x0; o1 = x1;
}

__device__ __forceinline__ int jax_start(int gidx) {
    uint32_t c0, c1, o0, o1;
    tf2x32(0u, 1u, 0u, 1u, c0, c1);
    tf2x32(c0, c1, 0u, (uint32_t)gidx, o0, o1);
    return (int)((o0 ^ o1) & 1023u);
}

// ---------------- grid barrier (80 blocks, all co-resident) ----------------
__device__ void grid_barrier() {
    __syncthreads();
    if (threadIdx.x == 0) {
        volatile unsigned int* vgen = &g_bar_gen;
        unsigned int gen = *vgen;
        __threadfence();
        unsigned int ticket = atomicAdd(&g_bar_count, 1u);
        if (ticket == NGROUP - 1) {
            g_bar_count = 0u;
            __threadfence();
            atomicAdd(&g_bar_gen, 1u);
        } else {
            while (*vgen == gen) { __nanosleep(32); }
        }
        __threadfence();
    }
    __syncthreads();
}

__device__ __forceinline__ float sq3(float a, float b, float c) {
    // ((a*a + b*b) + c*c), non-fused (reference-critical math)
    return __fadd_rn(__fadd_rn(__fmul_rn(a, a), __fmul_rn(b, b)), __fmul_rn(c, c));
}

// ---------------- main persistent kernel ----------------
__global__ void __launch_bounds__(NTHR, 1)
kmeans_kernel(const float* __restrict__ pos, float* __restrict__ out, int out_size) {
    __shared__ float4   sP[NPG];          // points, w = |p|^2                  16384 B
    __shared__ float4   sCa[MCENT];       // centroids (-2x,-2y,-2z,|c|^2)       8192 B
    __shared__ float    sDrift[MCENT];    //                                     2048 B
    __shared__ uint8_t  whist[32][MCENT]; //                                    16384 B
    __shared__ uint16_t sortIdx[NPG];     //                                     2048 B
    __shared__ uint16_t sCnt[MCENT];
    __shared__ uint16_t sOff[MCENT];
    __shared__ uint32_t sWsum[16];
    __shared__ uint32_t redV[2][16];
    __shared__ uint32_t redI[2][16];
    __shared__ uint32_t sDmax16[16];
    __shared__ float    redF[16];
    __shared__ float    sScore;
    __shared__ int      sStart;
    __shared__ uint16_t wl[NPG];          // worklist of needy points            2048 B
    __shared__ int      wlN;
    __shared__ uint16_t sLbl[NPG];        // scan results                        2048 B
    __shared__ float    sUb[NPG];         //                                     4096 B
    __shared__ float    sLb[NPG];         //                                     4096 B

    const int g = blockIdx.x;
    const int t = threadIdx.x;
    const int b = g & (BEX - 1);
    const float* pb = pos + (size_t)b * NPG * 3;

    // two points per thread: A = t, B = t + 512
    const float pxA = pb[t * 3 + 0], pyA = pb[t * 3 + 1], pzA = pb[t * 3 + 2];
    const float pxB = pb[(t + NTHR) * 3 + 0], pyB = pb[(t + NTHR) * 3 + 1], pzB = pb[(t + NTHR) * 3 + 2];
    const float p2A = sq3(pxA, pyA, pzA);
    const float p2B = sq3(pxB, pyB, pzB);
    sP[t]        = make_float4(pxA, pyA, pzA, p2A);
    sP[t + NTHR] = make_float4(pxB, pyB, pzB, p2B);
    if (t == NTHR - 1) sStart = jax_start(g);
    __syncthreads();

    const int wid = t >> 5, lane = t & 31;
    const uint32_t below = (1u << lane) - 1u;

    // ================= FPS init (R4-identical structure & math) =================
    int last = sStart;
    float mindA = FINF, mindB = FINF;
    for (int k = 0; k < MCENT; ++k) {
        float4 q = sP[last];
        if (t == 0)
            sCa[k] = make_float4(__fmul_rn(-2.0f, q.x), __fmul_rn(-2.0f, q.y),
                                 __fmul_rn(-2.0f, q.z), sq3(q.x, q.y, q.z));
        {
            float dx = __fsub_rn(pxA, q.x), dy = __fsub_rn(pyA, q.y), dz = __fsub_rn(pzA, q.z);
            mindA = fminf(mindA, sq3(dx, dy, dz));
        }
        {
            float dx = __fsub_rn(pxB, q.x), dy = __fsub_rn(pyB, q.y), dz = __fsub_rn(pzB, q.z);
            mindB = fminf(mindB, sq3(dx, dy, dz));
        }
        uint32_t bA = __float_as_uint(mindA);
        uint32_t bB = __float_as_uint(mindB);
        uint32_t val = (bB > bA) ? bB : bA;
        uint32_t idx = (bB > bA) ? (uint32_t)(t + NTHR) : (uint32_t)t;
        uint32_t wm  = __reduce_max_sync(0xffffffffu, val);
        uint32_t cnd = (val == wm) ? idx : 0xFFFFu;
        uint32_t wix = __reduce_min_sync(0xffffffffu, cnd);
        int par = k & 1;
        if (lane == 0) { redV[par][wid] = wm; redI[par][wid] = wix; }
        __syncthreads();
        uint32_t v  = (lane < 16) ? redV[par][lane] : 0u;
        uint32_t gm = __reduce_max_sync(0xffffffffu, v);
        uint32_t cm = (lane < 16 && v == gm) ? redI[par][lane] : 0xFFFFu;
        last = (int)__reduce_min_sync(0xffffffffu, cm);
    }
    __syncthreads();

    // ================= k-means loop (global lockstep) =================
    int bjA = 0, bjB = 0;
    float ubA = 0.f, lbA = 0.f, ubB = 0.f, lbB = 0.f;

    for (int iter = 0; iter < MAXIT; ++iter) {
        bool scanA = true, scanB = true;

        if (iter > 0) {
            // dmax from last update (sDmax16 visible after grid_barrier)
            uint32_t dm = (lane < 16) ? sDmax16[lane] : 0u;
            float dmax = __uint_as_float(__reduce_max_sync(0xffffffffu, dm));
            // ---- point A skip test (conservative; cannot change fp argmin) ----
            {
                float UB = ubA + sDrift[bjA] + EPS_DR;
                float LB = lbA - dmax - EPS_DR;
                bool keep = (LB > 0.f) && (LB * LB - UB * UB > MARGIN);
                if (!keep) {   // tighten ub with one exact distance, retest
                    float4 c = sCa[bjA];
                    float F = __fmaf_rn(pzA, c.z, __fmaf_rn(pyA, c.y, __fmaf_rn(pxA, c.x, c.w)));
                    float ut = sqrtf(fmaxf(F + p2A, 0.f) + EPS_D2);
                    UB = fminf(UB, ut);
                    keep = (LB > 0.f) && (LB * LB - UB * UB > MARGIN);
                }
                ubA = UB; lbA = LB; scanA = !keep;
            }
            // ---- point B ----
            {
                float UB = ubB + sDrift[bjB] + EPS_DR;
                float LB = lbB - dmax - EPS_DR;
                bool keep = (LB > 0.f) && (LB * LB - UB * UB > MARGIN);
                if (!keep) {
                    float4 c = sCa[bjB];
                    float F = __fmaf_rn(pzB, c.z, __fmaf_rn(pyB, c.y, __fmaf_rn(pxB, c.x, c.w)));
                    float ut = sqrtf(fmaxf(F + p2B, 0.f) + EPS_D2);
                    UB = fminf(UB, ut);
                    keep = (LB > 0.f) && (LB * LB - UB * UB > MARGIN);
                }
                ubB = UB; lbB = LB; scanB = !keep;
            }
        }

        int W;
        if (iter == 0) {
            W = NPG + 1;                      // force full-scan path, no list
        } else {
            if (t == 0) wlN = 0;
            __syncthreads();
            unsigned mA = __ballot_sync(0xffffffffu, scanA);
            unsigned mB = __ballot_sync(0xffffffffu, scanB);
            int ca = __popc(mA), cb = __popc(mB);
            int basew = 0;
            if (lane == 0 && (ca + cb) > 0) basew = atomicAdd(&wlN, ca + cb);
            basew = __shfl_sync(0xffffffffu, basew, 0);
            if (scanA) wl[basew + __popc(mA & below)] = (uint16_t)t;
            if (scanB) wl[basew + ca + __popc(mB & below)] = (uint16_t)(t + NTHR);
            __syncthreads();
            W = wlN;
        }

        if (W > 768) {
            // ---- full scan, both points, R4-identical best/index decisions ----
            float bFA = FINF, sFA = FINF, bFB = FINF, sFB = FINF;
            int ja = 0, jb = 0;
            #pragma unroll 8
            for (int j = 0; j < MCENT; ++j) {
                float4 c = sCa[j];
                float FA = __fmaf_rn(pzA, c.z, __fmaf_rn(pyA, c.y, __fmaf_rn(pxA, c.x, c.w)));
                float FB = __fmaf_rn(pzB, c.z, __fmaf_rn(pyB, c.y, __fmaf_rn(pxB, c.x, c.w)));
                if (FA < bFA) { sFA = bFA; bFA = FA; ja = j; } else if (FA < sFA) sFA = FA;
                if (FB < bFB) { sFB = bFB; bFB = FB; jb = j; } else if (FB < sFB) sFB = FB;
            }
            bjA = ja; bjB = jb;
            ubA = sqrtf(fmaxf(bFA + p2A, 0.f) + EPS_D2);
            lbA = sqrtf(fmaxf(sFA + p2A - EPS_D2, 0.f));
            ubB = sqrtf(fmaxf(bFB + p2B, 0.f) + EPS_D2);
            lbB = sqrtf(fmaxf(sFB + p2B - EPS_D2, 0.f));
        } else {
            // ---- cooperative worklist scan: 4 threads/point, 128 centroids each ----
            for (int it0 = 0; it0 < W; it0 += 128) {
                int item = it0 + (t >> 2);
                int part = t & 3;
                float qx = 0.f, qy = 0.f, qz = 0.f, q2 = 0.f;
                int pi = 0;
                if (item < W) {
                    pi = wl[item];
                    float4 P = sP[pi];
                    qx = P.x; qy = P.y; qz = P.z; q2 = P.w;
                }
                float bF = FINF, sF = FINF; int bj = part << 7;
                int j0 = part << 7;
                #pragma unroll 8
                for (int jj = 0; jj < 128; ++jj) {
                    float4 c = sCa[j0 + jj];
                    float F = __fmaf_rn(qz, c.z, __fmaf_rn(qy, c.y, __fmaf_rn(qx, c.x, c.w)));
                    if (F < bF) { sF = bF; bF = F; bj = j0 + jj; } else if (F < sF) sF = F;
                }
                // exact lexicographic merge across the 4 partitions (butterfly)
                #pragma unroll
                for (int d = 1; d <= 2; d <<= 1) {
                    float oF = __shfl_xor_sync(0xffffffffu, bF, d);
                    int   oj = __shfl_xor_sync(0xffffffffu, bj, d);
                    float oS = __shfl_xor_sync(0xffffffffu, sF, d);
                    bool take = (oF < bF) || (oF == bF && oj < bj);
                    float loser = take ? bF : oF;
                    if (take) { bF = oF; bj = oj; }
                    sF = fminf(fminf(sF, oS), loser);
                }
                if (item < W && part == 0) {
                    sLbl[pi] = (uint16_t)bj;
                    sUb[pi] = sqrtf(fmaxf(bF + q2, 0.f) + EPS_D2);
                    sLb[pi] = sqrtf(fmaxf(sF + q2 - EPS_D2, 0.f));
                }
            }
            __syncthreads();
            if (scanA) { bjA = sLbl[t];        ubA = sUb[t];        lbA = sLb[t]; }
            if (scanB) { bjB = sLbl[t + NTHR]; ubB = sUb[t + NTHR]; lbB = sLb[t + NTHR]; }
        }

        // ---- deterministic stable counting sort of points by cluster ----
        ((uint4*)whist)[t * 2]     = make_uint4(0u, 0u, 0u, 0u);
        ((uint4*)whist)[t * 2 + 1] = make_uint4(0u, 0u, 0u, 0u);
        __syncthreads();

        uint32_t mmA = __match_any_sync(0xffffffffu, (uint32_t)bjA);
        int riwA = __popc(mmA & below);
        if (riwA == 0) whist[wid][bjA] = (uint8_t)__popc(mmA);
        uint32_t mmB = __match_any_sync(0xffffffffu, (uint32_t)bjB);
        int riwB = __popc(mmB & below);
        if (riwB == 0) whist[16 + wid][bjB] = (uint8_t)__popc(mmB);
        __syncthreads();

        uint32_t run = 0;
        #pragma unroll
        for (int w = 0; w < 32; ++w) {
            uint32_t v = whist[w][t];
            whist[w][t] = (uint8_t)run;
            run += v;
        }
        sCnt[t] = (uint16_t)run;

        uint32_t x = run;
        #pragma unroll
        for (int o = 1; o < 32; o <<= 1) {
            uint32_t y = __shfl_up_sync(0xffffffffu, x, o);
            if (lane >= o) x += y;
        }
        uint32_t exclInWarp = x - run;
        if (lane == 31) sWsum[wid] = x;
        __syncthreads();
        if (wid == 0) {
            uint32_t wv = (lane < 16) ? sWsum[lane] : 0u;
            uint32_t xx = wv;
            #pragma unroll
            for (int o = 1; o < 16; o <<= 1) {
                uint32_t y = __shfl_up_sync(0xffffffffu, xx, o);
                if (lane >= o) xx += y;
            }
            if (lane < 16) sWsum[lane] = xx - wv;
        }
        __syncthreads();
        sOff[t] = (uint16_t)(sWsum[wid] + exclInWarp);
        __syncthreads();

        {
            uint32_t rkA = (uint32_t)sOff[bjA] + whist[wid][bjA] + (uint32_t)riwA;
            sortIdx[rkA] = (uint16_t)t;
            uint32_t rkB = (uint32_t)sOff[bjB] + whist[16 + wid][bjB] + (uint32_t)riwB;
            sortIdx[rkB] = (uint16_t)(t + NTHR);
        }
        __syncthreads();

        // ---- per-cluster ordered fold + centroid update + drift + convergence ----
        int moved = 0;
        float drift;
        {
            uint32_t n = sCnt[t], base = sOff[t];
            float sx = 0.f, sy = 0.f, sz = 0.f;
            for (uint32_t k2 = 0; k2 < n; ++k2) {
                float4 p = sP[sortIdx[base + k2]];
                sx = __fadd_rn(sx, p.x);
                sy = __fadd_rn(sy, p.y);
                sz = __fadd_rn(sz, p.z);
            }
            float4 cs = sCa[t];
            float ocx = __fmul_rn(-0.5f, cs.x);   // exact recovery
            float ocy = __fmul_rn(-0.5f, cs.y);
            float ocz = __fmul_rn(-0.5f, cs.z);
            float cntf = (float)n;
            float nx, ny, nz;
            if (n > 0) {
                nx = __fdiv_rn(sx, cntf); ny = __fdiv_rn(sy, cntf); nz = __fdiv_rn(sz, cntf);
            } else {
                nx = ocx; ny = ocy; nz = ocz;
            }
            float dx = __fsub_rn(ocx, nx), dy = __fsub_rn(ocy, ny), dz = __fsub_rn(ocz, nz);
            drift = sqrtf(sq3(dx, dy, dz));
            moved = !(drift < TOLF);
            sCa[t] = make_float4(__fmul_rn(-2.0f, nx), __fmul_rn(-2.0f, ny),
                                 __fmul_rn(-2.0f, nz), sq3(nx, ny, nz));
            sDrift[t] = drift;
        }
        uint32_t wmx = __reduce_max_sync(0xffffffffu, __float_as_uint(drift));
        if (lane == 0) sDmax16[wid] = wmx;
        int any = __syncthreads_or(moved);
        if (t == 0 && any) atomicOr(&g_flags[iter], 1);
        grid_barrier();
        int notdone = *((volatile int*)&g_flags[iter]);
        if (!notdone) break;
    }

    // ================= score: L1 to assigned (final) centroids =================
    {
        float4 ca = sCa[bjA];
        float cax = __fmul_rn(-0.5f, ca.x), cay = __fmul_rn(-0.5f, ca.y), caz = __fmul_rn(-0.5f, ca.z);
        float4 cb = sCa[bjB];
        float cbx = __fmul_rn(-0.5f, cb.x), cby = __fmul_rn(-0.5f, cb.y), cbz = __fmul_rn(-0.5f, cb.z);
        float s = fabsf(pxA - cax) + fabsf(pyA - cay) + fabsf(pzA - caz)
                + fabsf(pxB - cbx) + fabsf(pyB - cby) + fabsf(pzB - cbz);
        #pragma unroll
        for (int off = 16; off > 0; off >>= 1)
            s += __shfl_down_sync(0xffffffffu, s, off);
        if (lane == 0) redF[wid] = s;
        __syncthreads();
        if (wid == 0) {
            float v = (lane < 16) ? redF[lane] : 0.f;
            #pragma unroll
            for (int off = 8; off > 0; off >>= 1)
                v += __shfl_down_sync(0xffffffffu, v, off);
            if (lane == 0) sScore = v;
        }
        __syncthreads();
    }

    // ================= outputs: [classification | centroids | scores] =================
    int ci = g * NPG + t;
    if (ci < out_size) out[ci] = (float)bjA;
    int ci2 = g * NPG + NTHR + t;
    if (ci2 < out_size) out[ci2] = (float)bjB;
    {
        int base = NGROUP * NPG + g * (MCENT * 3) + t * 3;
        if (base + 2 < out_size) {
            float4 cs = sCa[t];
            out[base + 0] = __fmul_rn(-0.5f, cs.x);
            out[base + 1] = __fmul_rn(-0.5f, cs.y);
            out[base + 2] = __fmul_rn(-0.5f, cs.z);
        }
    }
    if (t == 0) {
        int si = NGROUP * NPG + NGROUP * MCENT * 3 + g;
        if (si < out_size) out[si] = sScore;
    }
}

extern "C" void kernel_launch(void* const* d_in, const int* in_sizes, int n_in,
                              void* d_out, int out_size) {
    const float* pos = (const float*)d_in[0];
    void* flagsAddr = nullptr;
    cudaGetSymbolAddress(&flagsAddr, g_flags);
    cudaMemsetAsync(flagsAddr, 0, sizeof(int) * (MAXIT + 1), 0);
    kmeans_kernel<<<NGROUP, NTHR>>>(pos, (float*)d_out, out_size);
}

// round 8
// speedup vs baseline: 1.5207x; 1.5207x over previous
#include <cuda_runtime.h>
#include <cstdint>

#define NGROUP 80
#define BEX 8
#define NPG 1024
#define MCENT 512
#define NTHR 512
#define MAXIT 300
#define TOLF 1e-3f
#define FINF __int_as_float(0x7f800000)

// ---------------- device globals (no allocation allowed) ----------------
__device__ int g_flags[MAXIT + 1];
__device__ unsigned int g_bar_count;   // returns to 0 after each barrier
__device__ unsigned int g_bar_gen;     // monotonically increasing across replays (safe)

// ---------------- threefry2x32 (exact JAX PRNG, partitionable scheme) ----------------
__device__ __forceinline__ uint32_t rotl32(uint32_t x, int d) { return (x << d) | (x >> (32 - d)); }

__device__ __forceinline__ void tf2x32(uint32_t k0, uint32_t k1, uint32_t x0, uint32_t x1,
                                       uint32_t& o0, uint32_t& o1) {
    uint32_t ks0 = k0, ks1 = k1, ks2 = k0 ^ k1 ^ 0x1BD11BDAu;
#define RND(r) { x0 += x1; x1 = rotl32(x1, r); x1 ^= x0; }
    x0 += ks0; x1 += ks1;
    RND(13) RND(15) RND(26) RND(6)   x0 += ks1; x1 += ks2 + 1u;
    RND(17) RND(29) RND(16) RND(24)  x0 += ks2; x1 += ks0 + 2u;
    RND(13) RND(15) RND(26) RND(6)   x0 += ks0; x1 += ks1 + 3u;
    RND(17) RND(29) RND(16) RND(24)  x0 += ks1; x1 += ks2 + 4u;
    RND(13) RND(15) RND(26) RND(6)   x0 += ks2; x1 += ks0 + 5u;
#undef RND
    o0 = x0; o1 = x1;
}

// starts[g] = jax.random.randint(key(1), (80,), 0, 1024)[g], partitionable threefry
__device__ __forceinline__ int jax_start(int gidx) {
    uint32_t c0, c1, o0, o1;
    tf2x32(0u, 1u, 0u, 1u, c0, c1);
    tf2x32(c0, c1, 0u, (uint32_t)gidx, o0, o1);
    return (int)((o0 ^ o1) & 1023u);
}

// ---------------- grid barrier (80 blocks, all co-resident) ----------------
__device__ void grid_barrier() {
    __syncthreads();
    if (threadIdx.x == 0) {
        volatile unsigned int* vgen = &g_bar_gen;
        unsigned int gen = *vgen;
        __threadfence();
        unsigned int ticket = atomicAdd(&g_bar_count, 1u);
        if (ticket == NGROUP - 1) {
            g_bar_count = 0u;
            __threadfence();
            atomicAdd(&g_bar_gen, 1u);
        } else {
            while (*vgen == gen) { __nanosleep(32); }
        }
        __threadfence();
    }
    __syncthreads();
}

__device__ __forceinline__ float sq3(float a, float b, float c) {
    // ((a*a + b*b) + c*c), non-fused (reference-critical math)
    return __fadd_rn(__fadd_rn(__fmul_rn(a, a), __fmul_rn(b, b)), __fmul_rn(c, c));
}

// ---------------- main persistent kernel: FPS + k-means + score ----------------
__global__ void __launch_bounds__(NTHR, 1)
kmeans_kernel(const float* __restrict__ pos, float* __restrict__ out, int out_size) {
    __shared__ float4   sP[NPG];          // points                             16384 B
    __shared__ float4   sC[MCENT];        // centroids as (-2x,-2y,-2z,|c|^2)    8192 B
    __shared__ uint8_t  whist[32][MCENT]; // rows 0-15: A-points, 16-31: B      16384 B
    __shared__ uint16_t sortIdx[NPG];     // cluster-sorted point indices        2048 B
    __shared__ uint16_t sCnt[MCENT];
    __shared__ uint16_t sOff[MCENT];
    __shared__ uint32_t sWsum[16];
    __shared__ uint32_t redV[2][16];
    __shared__ uint32_t redI[2][16];
    __shared__ float    redF[16];
    __shared__ float    sScore;
    __shared__ int      sStart;

    const int g = blockIdx.x;
    const int t = threadIdx.x;
    const int b = g & (BEX - 1);           // group g = r*B + b  ->  example b
    const float* pb = pos + (size_t)b * NPG * 3;

    // two points per thread: A = t, B = t + 512
    const float pxA = pb[t * 3 + 0], pyA = pb[t * 3 + 1], pzA = pb[t * 3 + 2];
    const float pxB = pb[(t + NTHR) * 3 + 0], pyB = pb[(t + NTHR) * 3 + 1], pzB = pb[(t + NTHR) * 3 + 2];
    sP[t]        = make_float4(pxA, pyA, pzA, 0.f);
    sP[t + NTHR] = make_float4(pxB, pyB, pzB, 0.f);
    if (t == NTHR - 1) sStart = jax_start(g);    // merged starts kernel (exact)
    __syncthreads();

    const int wid = t >> 5, lane = t & 31;

    // ================= FPS init (R4-identical structure & math) =================
    int last = sStart;
    float mindA = FINF;
    float mindB = FINF;
    for (int k = 0; k < MCENT; ++k) {
        float4 q = sP[last];                   // uniform broadcast
        if (t == 0)
            sC[k] = make_float4(__fmul_rn(-2.0f, q.x), __fmul_rn(-2.0f, q.y),
                                __fmul_rn(-2.0f, q.z), sq3(q.x, q.y, q.z));
        {
            float dx = __fsub_rn(pxA, q.x), dy = __fsub_rn(pyA, q.y), dz = __fsub_rn(pzA, q.z);
            mindA = fminf(mindA, sq3(dx, dy, dz));
        }
        {
            float dx = __fsub_rn(pxB, q.x), dy = __fsub_rn(pyB, q.y), dz = __fsub_rn(pzB, q.z);
            mindB = fminf(mindB, sq3(dx, dy, dz));
        }
        // argmax(mind), FIRST-index tie-break: value-max + min-index-among-max.
        uint32_t bA = __float_as_uint(mindA);  // positive-float bits monotonic
        uint32_t bB = __float_as_uint(mindB);
        uint32_t val = (bB > bA) ? bB : bA;
        uint32_t idx = (bB > bA) ? (uint32_t)(t + NTHR) : (uint32_t)t;  // tie -> A (smaller idx)
        uint32_t wm  = __reduce_max_sync(0xffffffffu, val);
        uint32_t cnd = (val == wm) ? idx : 0xFFFFu;
        uint32_t wix = __reduce_min_sync(0xffffffffu, cnd);
        int par = k & 1;
        if (lane == 0) { redV[par][wid] = wm; redI[par][wid] = wix; }
        __syncthreads();
        uint32_t v  = (lane < 16) ? redV[par][lane] : 0u;
        uint32_t gm = __reduce_max_sync(0xffffffffu, v);
        uint32_t cm = (lane < 16 && v == gm) ? redI[par][lane] : 0xFFFFu;
        last = (int)__reduce_min_sync(0xffffffffu, cm);   // smallest global index
    }
    __syncthreads();

    // ================= k-means loop (global lockstep) =================
    int bjA = 0, bjB = 0;
    for (int iter = 0; iter < MAXIT; ++iter) {
        // ---- assign pass 1: per-64-block minima of F = c2 - 2*p.c (no index) ----
        float mA[8], mB[8];
        #pragma unroll
        for (int blk = 0; blk < 8; ++blk) {
            float bmA = FINF, bmB = FINF;
            const float4* cbase = sC + (blk << 6);
            #pragma unroll 8
            for (int jj = 0; jj < 64; ++jj) {
                float4 c = cbase[jj];
                float FA = __fmaf_rn(pzA, c.z, __fmaf_rn(pyA, c.y, __fmaf_rn(pxA, c.x, c.w)));
                float FB = __fmaf_rn(pzB, c.z, __fmaf_rn(pyB, c.y, __fmaf_rn(pxB, c.x, c.w)));
                bmA = fminf(bmA, FA);
                bmB = fminf(bmB, FB);
            }
            mA[blk] = bmA;
            mB[blk] = bmB;
        }
        // merge: strict '<' keeps the FIRST block achieving the min
        float bestA = mA[0]; int blkA = 0;
        float bestB = mB[0]; int blkB = 0;
        #pragma unroll
        for (int i = 1; i < 8; ++i) {
            if (mA[i] < bestA) { bestA = mA[i]; blkA = i; }
            if (mB[i] < bestB) { bestB = mB[i]; blkB = i; }
        }
        // ---- assign pass 2: rescan winning block, first j with F == best ----
        {
            int baseA = blkA << 6;
            int ja = MCENT;
            const float4* cA = sC + baseA;
            #pragma unroll 8
            for (int jj = 0; jj < 64; ++jj) {
                float4 c = cA[jj];
                float F = __fmaf_rn(pzA, c.z, __fmaf_rn(pyA, c.y, __fmaf_rn(pxA, c.x, c.w)));
                if (F == bestA) ja = min(ja, baseA + jj);   // first index among equals
            }
            bjA = ja;
        }
        {
            int baseB = blkB << 6;
            int jb = MCENT;
            const float4* cB = sC + baseB;
            #pragma unroll 8
            for (int jj = 0; jj < 64; ++jj) {
                float4 c = cB[jj];
                float F = __fmaf_rn(pzB, c.z, __fmaf_rn(pyB, c.y, __fmaf_rn(pxB, c.x, c.w)));
                if (F == bestB) jb = min(jb, baseB + jj);
            }
            bjB = jb;
        }

        // ---- deterministic stable counting sort of points by cluster ----
        ((uint4*)whist)[t * 2]     = make_uint4(0u, 0u, 0u, 0u);   // zero 16KB
        ((uint4*)whist)[t * 2 + 1] = make_uint4(0u, 0u, 0u, 0u);
        __syncthreads();

        uint32_t below = (1u << lane) - 1u;
        uint32_t mmA = __match_any_sync(0xffffffffu, (uint32_t)bjA);
        int riwA = __popc(mmA & below);
        if (riwA == 0) whist[wid][bjA] = (uint8_t)__popc(mmA);
        uint32_t mmB = __match_any_sync(0xffffffffu, (uint32_t)bjB);
        int riwB = __popc(mmB & below);
        if (riwB == 0) whist[16 + wid][bjB] = (uint8_t)__popc(mmB);
        __syncthreads();

        // per-cluster exclusive prefix over the 32 rows (in place) + counts
        uint32_t run = 0;
        #pragma unroll
        for (int w = 0; w < 32; ++w) {
            uint32_t v = whist[w][t];
            whist[w][t] = (uint8_t)run;
            run += v;
        }
        sCnt[t] = (uint16_t)run;

        // block-wide exclusive prefix sum over the 512 counts (16 warps)
        uint32_t x = run;
        #pragma unroll
        for (int o = 1; o < 32; o <<= 1) {
            uint32_t y = __shfl_up_sync(0xffffffffu, x, o);
            if (lane >= o) x += y;
        }
        uint32_t exclInWarp = x - run;
        if (lane == 31) sWsum[wid] = x;
        __syncthreads();
        if (wid == 0) {
            uint32_t wv = (lane < 16) ? sWsum[lane] : 0u;
            uint32_t xx = wv;
            #pragma unroll
            for (int o = 1; o < 16; o <<= 1) {
                uint32_t y = __shfl_up_sync(0xffffffffu, xx, o);
                if (lane >= o) xx += y;
            }
            if (lane < 16) sWsum[lane] = xx - wv;
        }
        __syncthreads();
        sOff[t] = (uint16_t)(sWsum[wid] + exclInWarp);
        __syncthreads();

        // scatter point indices; ascending-index order preserved per cluster
        {
            uint32_t rkA = (uint32_t)sOff[bjA] + whist[wid][bjA] + (uint32_t)riwA;
            sortIdx[rkA] = (uint16_t)t;
            uint32_t rkB = (uint32_t)sOff[bjB] + whist[16 + wid][bjB] + (uint32_t)riwB;
            sortIdx[rkB] = (uint16_t)(t + NTHR);
        }
        __syncthreads();

        // per-cluster ordered fold + centroid update + convergence
        int moved = 0;
        {
            uint32_t n = sCnt[t], base = sOff[t];
            float sx = 0.f, sy = 0.f, sz = 0.f;
            for (uint32_t k2 = 0; k2 < n; ++k2) {
                float4 p = sP[sortIdx[base + k2]];
                sx = __fadd_rn(sx, p.x);
                sy = __fadd_rn(sy, p.y);
                sz = __fadd_rn(sz, p.z);
            }
            float4 cs = sC[t];
            float ocx = __fmul_rn(-0.5f, cs.x);   // exact recovery
            float ocy = __fmul_rn(-0.5f, cs.y);
            float ocz = __fmul_rn(-0.5f, cs.z);
            float cntf = (float)n;
            float nx, ny, nz;
            if (n > 0) {
                nx = __fdiv_rn(sx, cntf); ny = __fdiv_rn(sy, cntf); nz = __fdiv_rn(sz, cntf);
            } else {
                nx = ocx; ny = ocy; nz = ocz;
            }
            float dx = __fsub_rn(ocx, nx), dy = __fsub_rn(ocy, ny), dz = __fsub_rn(ocz, nz);
            moved = !(sqrtf(sq3(dx, dy, dz)) < TOLF);
            sC[t] = make_float4(__fmul_rn(-2.0f, nx), __fmul_rn(-2.0f, ny),
                                __fmul_rn(-2.0f, nz), sq3(nx, ny, nz));
        }
        int any = __syncthreads_or(moved);
        if (t == 0 && any) atomicOr(&g_flags[iter], 1);
        grid_barrier();
        int notdone = *((volatile int*)&g_flags[iter]);
        if (!notdone) break;   // all blocks agree -> same iteration count everywhere
    }

    // ================= score: L1 to assigned (final) centroids =================
    {
        float4 ca = sC[bjA];
        float cax = __fmul_rn(-0.5f, ca.x), cay = __fmul_rn(-0.5f, ca.y), caz = __fmul_rn(-0.5f, ca.z);
        float4 cb = sC[bjB];
        float cbx = __fmul_rn(-0.5f, cb.x), cby = __fmul_rn(-0.5f, cb.y), cbz = __fmul_rn(-0.5f, cb.z);
        float s = fabsf(pxA - cax) + fabsf(pyA - cay) + fabsf(pzA - caz)
                + fabsf(pxB - cbx) + fabsf(pyB - cby) + fabsf(pzB - cbz);
        #pragma unroll
        for (int off = 16; off > 0; off >>= 1)
            s += __shfl_down_sync(0xffffffffu, s, off);
        if (lane == 0) redF[wid] = s;
        __syncthreads();
        if (wid == 0) {
            float v = (lane < 16) ? redF[lane] : 0.f;
            #pragma unroll
            for (int off = 8; off > 0; off >>= 1)
                v += __shfl_down_sync(0xffffffffu, v, off);
            if (lane == 0) sScore = v;
        }
        __syncthreads();
    }

    // ================= outputs: [classification | centroids | scores] =================
    int ci = g * NPG + t;
    if (ci < out_size) out[ci] = (float)bjA;
    int ci2 = g * NPG + NTHR + t;
    if (ci2 < out_size) out[ci2] = (float)bjB;
    {
        int base = NGROUP * NPG + g * (MCENT * 3) + t * 3;
        if (base + 2 < out_size) {
            float4 cs = sC[t];
            out[base + 0] = __fmul_rn(-0.5f, cs.x);
            out[base + 1] = __fmul_rn(-0.5f, cs.y);
            out[base + 2] = __fmul_rn(-0.5f, cs.z);
        }
    }
    if (t == 0) {
        int si = NGROUP * NPG + NGROUP * MCENT * 3 + g;
        if (si < out_size) out[si] = sScore;
    }
}

extern "C" void kernel_launch(void* const* d_in, const int* in_sizes, int n_in,
                              void* d_out, int out_size) {
    const float* pos = (const float*)d_in[0];
    void* flagsAddr = nullptr;
    cudaGetSymbolAddress(&flagsAddr, g_flags);
    cudaMemsetAsync(flagsAddr, 0, sizeof(int) * (MAXIT + 1), 0);
    kmeans_kernel<<<NGROUP, NTHR>>>(pos, (float*)d_out, out_size);
}

// round 9
// speedup vs baseline: 2.4575x; 1.6160x over previous
#include <cuda_runtime.h>
#include <cstdint>

#define NGROUP 80
#define BEX 8
#define NPG 1024
#define MCENT 512
#define NTHR 512
#define MAXIT 300
#define TOLF 1e-3f
#define FINF __int_as_float(0x7f800000)

// ---------------- device globals (no allocation allowed) ----------------
__device__ unsigned int g_bar_count;   // packed: low 16 = arrivals, high = moved count; returns to 0
__device__ unsigned int g_bar_gen;     // monotonically increasing across replays (safe)
__device__ int g_notdone;              // published by last arriver before gen flip

// ---------------- threefry2x32 (exact JAX PRNG, partitionable scheme) ----------------
__device__ __forceinline__ uint32_t rotl32(uint32_t x, int d) { return (x << d) | (x >> (32 - d)); }

__device__ __forceinline__ void tf2x32(uint32_t k0, uint32_t k1, uint32_t x0, uint32_t x1,
                                       uint32_t& o0, uint32_t& o1) {
    uint32_t ks0 = k0, ks1 = k1, ks2 = k0 ^ k1 ^ 0x1BD11BDAu;
#define RND(r) { x0 += x1; x1 = rotl32(x1, r); x1 ^= x0; }
    x0 += ks0; x1 += ks1;
    RND(13) RND(15) RND(26) RND(6)   x0 += ks1; x1 += ks2 + 1u;
    RND(17) RND(29) RND(16) RND(24)  x0 += ks2; x1 += ks0 + 2u;
    RND(13) RND(15) RND(26) RND(6)   x0 += ks0; x1 += ks1 + 3u;
    RND(17) RND(29) RND(16) RND(24)  x0 += ks1; x1 += ks2 + 4u;
    RND(13) RND(15) RND(26) RND(6)   x0 += ks2; x1 += ks0 + 5u;
#undef RND
    o0 = x0; o1 = x1;
}

// starts[g] = jax.random.randint(key(1), (80,), 0, 1024)[g], partitionable threefry
__device__ __forceinline__ int jax_start(int gidx) {
    uint32_t c0, c1, o0, o1;
    tf2x32(0u, 1u, 0u, 1u, c0, c1);
    tf2x32(c0, c1, 0u, (uint32_t)gidx, o0, o1);
    return (int)((o0 ^ o1) & 1023u);
}

// ---------------- grid barrier with fused any-moved reduction ----------------
// Every block passes its local 'moved' flag; all blocks receive OR over all blocks.
__device__ __forceinline__ int grid_barrier_any(int moved) {
    __shared__ int sNotdone;
    __syncthreads();
    if (threadIdx.x == 0) {
        volatile unsigned int* vgen = &g_bar_gen;
        unsigned int gen = *vgen;
        __threadfence();
        unsigned int ticket = atomicAdd(&g_bar_count, 1u + (moved ? 0x10000u : 0u));
        if ((ticket & 0xFFFFu) == NGROUP - 1) {
            unsigned int movedCnt = (ticket >> 16) + (moved ? 1u : 0u);
            g_bar_count = 0u;
            g_notdone = (movedCnt != 0u) ? 1 : 0;
            __threadfence();
            atomicAdd(&g_bar_gen, 1u);
        } else {
            while (*vgen == gen) { __nanosleep(32); }
        }
        __threadfence();
        sNotdone = *((volatile int*)&g_notdone);
    }
    __syncthreads();
    return sNotdone;
}

__device__ __forceinline__ float sq3(float a, float b, float c) {
    // ((a*a + b*b) + c*c), non-fused (reference-critical math)
    return __fadd_rn(__fadd_rn(__fmul_rn(a, a), __fmul_rn(b, b)), __fmul_rn(c, c));
}

// ---------------- main persistent kernel: FPS + k-means + score ----------------
__global__ void __launch_bounds__(NTHR, 1)
kmeans_kernel(const float* __restrict__ pos, float* __restrict__ out, int out_size) {
    __shared__ float4   sP[NPG];          // points                             16384 B
    __shared__ float4   sC[MCENT];        // centroids as (-2x,-2y,-2z,|c|^2)    8192 B
    __shared__ uint8_t  whist[32][MCENT]; // rows 0-15: A-points, 16-31: B      16384 B
    __shared__ uint16_t sortIdx[NPG];     // cluster-sorted point indices        2048 B
    __shared__ uint16_t sCnt[MCENT];
    __shared__ uint16_t sOff[MCENT];
    __shared__ uint32_t sWsum[16];
    __shared__ uint32_t redV[2][16];
    __shared__ uint32_t redI[2][16];
    __shared__ float    redF[16];
    __shared__ float    sScore;
    __shared__ int      sStart;

    const int g = blockIdx.x;
    const int t = threadIdx.x;
    const int b = g & (BEX - 1);           // group g = r*B + b  ->  example b
    const float* pb = pos + (size_t)b * NPG * 3;

    // two points per thread: A = t, B = t + 512
    const float pxA = pb[t * 3 + 0], pyA = pb[t * 3 + 1], pzA = pb[t * 3 + 2];
    const float pxB = pb[(t + NTHR) * 3 + 0], pyB = pb[(t + NTHR) * 3 + 1], pzB = pb[(t + NTHR) * 3 + 2];
    sP[t]        = make_float4(pxA, pyA, pzA, 0.f);
    sP[t + NTHR] = make_float4(pxB, pyB, pzB, 0.f);
    if (t == NTHR - 1) sStart = jax_start(g);    // merged starts kernel (exact)
    __syncthreads();

    const int wid = t >> 5, lane = t & 31;

    // ================= FPS init (R4-identical structure & math) =================
    int last = sStart;
    float mindA = FINF;
    float mindB = FINF;
    for (int k = 0; k < MCENT; ++k) {
        float4 q = sP[last];                   // uniform broadcast
        if (t == 0)
            sC[k] = make_float4(__fmul_rn(-2.0f, q.x), __fmul_rn(-2.0f, q.y),
                                __fmul_rn(-2.0f, q.z), sq3(q.x, q.y, q.z));
        {
            float dx = __fsub_rn(pxA, q.x), dy = __fsub_rn(pyA, q.y), dz = __fsub_rn(pzA, q.z);
            mindA = fminf(mindA, sq3(dx, dy, dz));
        }
        {
            float dx = __fsub_rn(pxB, q.x), dy = __fsub_rn(pyB, q.y), dz = __fsub_rn(pzB, q.z);
            mindB = fminf(mindB, sq3(dx, dy, dz));
        }
        // argmax(mind), FIRST-index tie-break: value-max + min-index-among-max.
        uint32_t bA = __float_as_uint(mindA);  // positive-float bits monotonic
        uint32_t bB = __float_as_uint(mindB);
        uint32_t val = (bB > bA) ? bB : bA;
        uint32_t idx = (bB > bA) ? (uint32_t)(t + NTHR) : (uint32_t)t;  // tie -> A (smaller idx)
        uint32_t wm  = __reduce_max_sync(0xffffffffu, val);
        uint32_t cnd = (val == wm) ? idx : 0xFFFFu;
        uint32_t wix = __reduce_min_sync(0xffffffffu, cnd);
        int par = k & 1;
        if (lane == 0) { redV[par][wid] = wm; redI[par][wid] = wix; }
        __syncthreads();
        uint32_t v  = (lane < 16) ? redV[par][lane] : 0u;
        uint32_t gm = __reduce_max_sync(0xffffffffu, v);
        uint32_t cm = (lane < 16 && v == gm) ? redI[par][lane] : 0xFFFFu;
        last = (int)__reduce_min_sync(0xffffffffu, cm);   // smallest global index
    }
    __syncthreads();

    // ================= k-means loop (global lockstep) =================
    int bjA = 0, bjB = 0;
    for (int iter = 0; iter < MAXIT; ++iter) {
        // ---- assign: argmin_j (c2 + px*(-2cx) + py*(-2cy) + pz*(-2cz)) ----
        float bestA = FINF;
        float bestB = FINF;
        bjA = 0; bjB = 0;
        #pragma unroll 8
        for (int j = 0; j < MCENT; ++j) {
            float4 c = sC[j];
            float aA = __fmaf_rn(pzA, c.z, __fmaf_rn(pyA, c.y, __fmaf_rn(pxA, c.x, c.w)));
            float aB = __fmaf_rn(pzB, c.z, __fmaf_rn(pyB, c.y, __fmaf_rn(pxB, c.x, c.w)));
            if (aA < bestA) { bestA = aA; bjA = j; }   // strict '<' keeps first index
            if (aB < bestB) { bestB = aB; bjB = j; }
        }

        // ---- deterministic stable counting sort of points by cluster ----
        ((uint4*)whist)[t * 2]     = make_uint4(0u, 0u, 0u, 0u);   // zero 16KB
        ((uint4*)whist)[t * 2 + 1] = make_uint4(0u, 0u, 0u, 0u);
        __syncthreads();

        // per-warp stable ranks + per-warp histograms (A rows 0-15, B rows 16-31)
        uint32_t below = (1u << lane) - 1u;
        uint32_t mmA = __match_any_sync(0xffffffffu, (uint32_t)bjA);
        int riwA = __popc(mmA & below);
        if (riwA == 0) whist[wid][bjA] = (uint8_t)__popc(mmA);
        uint32_t mmB = __match_any_sync(0xffffffffu, (uint32_t)bjB);
        int riwB = __popc(mmB & below);
        if (riwB == 0) whist[16 + wid][bjB] = (uint8_t)__popc(mmB);
        __syncthreads();

        // per-cluster exclusive prefix over the 32 rows (in place) + counts
        uint32_t run = 0;
        #pragma unroll
        for (int w = 0; w < 32; ++w) {
            uint32_t v = whist[w][t];
            whist[w][t] = (uint8_t)run;
            run += v;
        }
        sCnt[t] = (uint16_t)run;

        // block-wide exclusive prefix sum over the 512 counts (16 warps)
        uint32_t x = run;
        #pragma unroll
        for (int o = 1; o < 32; o <<= 1) {
            uint32_t y = __shfl_up_sync(0xffffffffu, x, o);
            if (lane >= o) x += y;
        }
        uint32_t exclInWarp = x - run;
        if (lane == 31) sWsum[wid] = x;
        __syncthreads();
        if (wid == 0) {
            uint32_t wv = (lane < 16) ? sWsum[lane] : 0u;
            uint32_t xx = wv;
            #pragma unroll
            for (int o = 1; o < 16; o <<= 1) {
                uint32_t y = __shfl_up_sync(0xffffffffu, xx, o);
                if (lane >= o) xx += y;
            }
            if (lane < 16) sWsum[lane] = xx - wv;
        }
        __syncthreads();
        sOff[t] = (uint16_t)(sWsum[wid] + exclInWarp);
        __syncthreads();

        // scatter point indices; ascending-index order preserved per cluster
        {
            uint32_t rkA = (uint32_t)sOff[bjA] + whist[wid][bjA] + (uint32_t)riwA;
            sortIdx[rkA] = (uint16_t)t;
            uint32_t rkB = (uint32_t)sOff[bjB] + whist[16 + wid][bjB] + (uint32_t)riwB;
            sortIdx[rkB] = (uint16_t)(t + NTHR);
        }
        __syncthreads();

        // per-cluster ordered fold + centroid update + convergence
        int moved = 0;
        {
            uint32_t n = sCnt[t], base = sOff[t];
            float sx = 0.f, sy = 0.f, sz = 0.f;
            for (uint32_t k2 = 0; k2 < n; ++k2) {
                float4 p = sP[sortIdx[base + k2]];
                sx = __fadd_rn(sx, p.x);
                sy = __fadd_rn(sy, p.y);
                sz = __fadd_rn(sz, p.z);
            }
            float4 cs = sC[t];
            float ocx = __fmul_rn(-0.5f, cs.x);   // exact recovery
            float ocy = __fmul_rn(-0.5f, cs.y);
            float ocz = __fmul_rn(-0.5f, cs.z);
            float cntf = (float)n;
            float nx, ny, nz;
            if (n > 0) {
                nx = __fdiv_rn(sx, cntf); ny = __fdiv_rn(sy, cntf); nz = __fdiv_rn(sz, cntf);
            } else {
                nx = ocx; ny = ocy; nz = ocz;
            }
            float dx = __fsub_rn(ocx, nx), dy = __fsub_rn(ocy, ny), dz = __fsub_rn(ocz, nz);
            moved = !(sqrtf(sq3(dx, dy, dz)) < TOLF);
            sC[t] = make_float4(__fmul_rn(-2.0f, nx), __fmul_rn(-2.0f, ny),
                                __fmul_rn(-2.0f, nz), sq3(nx, ny, nz));
        }
        int any = __syncthreads_or(moved);
        int notdone = grid_barrier_any(any);
        if (!notdone) break;   // all blocks agree -> same iteration count everywhere
    }

    // ================= score: L1 to assigned (final) centroids =================
    {
        float4 ca = sC[bjA];
        float cax = __fmul_rn(-0.5f, ca.x), cay = __fmul_rn(-0.5f, ca.y), caz = __fmul_rn(-0.5f, ca.z);
        float4 cb = sC[bjB];
        float cbx = __fmul_rn(-0.5f, cb.x), cby = __fmul_rn(-0.5f, cb.y), cbz = __fmul_rn(-0.5f, cb.z);
        float s = fabsf(pxA - cax) + fabsf(pyA - cay) + fabsf(pzA - caz)
                + fabsf(pxB - cbx) + fabsf(pyB - cby) + fabsf(pzB - cbz);
        #pragma unroll
        for (int off = 16; off > 0; off >>= 1)
            s += __shfl_down_sync(0xffffffffu, s, off);
        if (lane == 0) redF[wid] = s;
        __syncthreads();
        if (wid == 0) {
            float v = (lane < 16) ? redF[lane] : 0.f;
            #pragma unroll
            for (int off = 8; off > 0; off >>= 1)
                v += __shfl_down_sync(0xffffffffu, v, off);
            if (lane == 0) sScore = v;
        }
        __syncthreads();
    }

    // ================= outputs: [classification | centroids | scores] =================
    int ci = g * NPG + t;
    if (ci < out_size) out[ci] = (float)bjA;
    int ci2 = g * NPG + NTHR + t;
    if (ci2 < out_size) out[ci2] = (float)bjB;
    {
        int base = NGROUP * NPG + g * (MCENT * 3) + t * 3;
        if (base + 2 < out_size) {
            float4 cs = sC[t];
            out[base + 0] = __fmul_rn(-0.5f, cs.x);
            out[base + 1] = __fmul_rn(-0.5f, cs.y);
            out[base + 2] = __fmul_rn(-0.5f, cs.z);
        }
    }
    if (t == 0) {
        int si = NGROUP * NPG + NGROUP * MCENT * 3 + g;
        if (si < out_size) out[si] = sScore;
    }
}

extern "C" void kernel_launch(void* const* d_in, const int* in_sizes, int n_in,
                              void* d_out, int out_size) {
    const float* pos = (const float*)d_in[0];
    kmeans_kernel<<<NGROUP, NTHR>>>(pos, (float*)d_out, out_size);
}